// round 14
// baseline (speedup 1.0000x reference)
#include <cuda_runtime.h>
#include <cuda_bf16.h>
#include <math.h>
#include <cstdint>

#define E_DIM 1024
#define M_DIM 4096
#define H_NUM 16
#define HD 64
#define B_SZ 4
#define NELEM (M_DIM * E_DIM)
#define WSZ (E_DIM * E_DIM)

// exp(-c*d) = exp2(-c*log2e*d).  c1=1/16, c2=3/16.
#define NSC1 (-0.09016844005555976f)   // -c1*log2e
#define NSC2 (-0.27050532016667927f)   // -c2*log2e
#define SC1  (0.18033688011111952f)    // +2*c1*log2e
#define SC2  (0.54101064033335854f)    // +2*c2*log2e

// bf16 hi/lo split buffers (inputs to GEMMs)
__device__ __nv_bfloat16 in_q_h[NELEM], in_q_l[NELEM];
__device__ __nv_bfloat16 in_k_h[NELEM], in_k_l[NELEM];
__device__ __nv_bfloat16 in_v_h[NELEM], in_v_l[NELEM];
__device__ __nv_bfloat16 w_h[5 * WSZ],  w_l[5 * WSZ];

// proj outputs (bf16 hi/lo), attention output (bf16 hi/lo)
__device__ __nv_bfloat16 o_q_h[NELEM],  o_q_l[NELEM];
__device__ __nv_bfloat16 o_k1_h[NELEM], o_k1_l[NELEM];
__device__ __nv_bfloat16 o_k2_h[NELEM], o_k2_l[NELEM];
__device__ __nv_bfloat16 o_v_h[NELEM],  o_v_l[NELEM];
__device__ __nv_bfloat16 ao_h[NELEM],   ao_l[NELEM];

// norms: [bh*1024 + t].  n_q2 raw q^2; n_k1/n_k2 pre-scaled by NSC1/NSC2.
__device__ float n_q2[64 * 1024];
__device__ float n_k1[64 * 1024];
__device__ float n_k2[64 * 1024];

// ===========================================================================
// helpers
// ===========================================================================
__device__ __forceinline__ uint32_t smem_u32(const void* p) {
    uint32_t a;
    asm("{ .reg .u64 t; cvta.to.shared.u64 t, %1; cvt.u32.u64 %0, t; }"
        : "=r"(a) : "l"(p));
    return a;
}
__device__ __forceinline__ void cp_async16(uint32_t dst, const void* src) {
    asm volatile("cp.async.cg.shared.global [%0], [%1], 16;"
                 :: "r"(dst), "l"(src));
}
__device__ __forceinline__ void cp_commit() {
    asm volatile("cp.async.commit_group;" ::: "memory");
}
__device__ __forceinline__ void cp_wait1() {
    asm volatile("cp.async.wait_group 1;" ::: "memory");
}
__device__ __forceinline__ void cp_wait0() {
    asm volatile("cp.async.wait_group 0;" ::: "memory");
}
__device__ __forceinline__ void ldsm4(uint32_t addr, uint32_t* r) {
    asm volatile("ldmatrix.sync.aligned.m8n8.x4.shared.b16 {%0,%1,%2,%3}, [%4];"
                 : "=r"(r[0]), "=r"(r[1]), "=r"(r[2]), "=r"(r[3]) : "r"(addr));
}
__device__ __forceinline__ void ldsm4t(uint32_t addr, uint32_t* r) {
    asm volatile("ldmatrix.sync.aligned.m8n8.x4.trans.shared.b16 {%0,%1,%2,%3}, [%4];"
                 : "=r"(r[0]), "=r"(r[1]), "=r"(r[2]), "=r"(r[3]) : "r"(addr));
}
__device__ __forceinline__ void mma16816(float* d, const uint32_t* a,
                                         const uint32_t* b) {
    asm volatile(
        "mma.sync.aligned.m16n8k16.row.col.f32.bf16.bf16.f32 "
        "{%0,%1,%2,%3}, {%4,%5,%6,%7}, {%8,%9}, {%0,%1,%2,%3};"
        : "+f"(d[0]), "+f"(d[1]), "+f"(d[2]), "+f"(d[3])
        : "r"(a[0]), "r"(a[1]), "r"(a[2]), "r"(a[3]), "r"(b[0]), "r"(b[1]));
}
__device__ __forceinline__ float ex2f(float x) {
    float y;
    asm("ex2.approx.ftz.f32 %0, %1;" : "=f"(y) : "f"(x));
    return y;
}
__device__ __forceinline__ void split2(float x, float y, uint32_t& hi, uint32_t& lo) {
    __nv_bfloat162 h = __float22bfloat162_rn(make_float2(x, y));
    float2 f = __bfloat1622float2(h);
    __nv_bfloat162 l = __float22bfloat162_rn(make_float2(x - f.x, y - f.y));
    hi = *reinterpret_cast<uint32_t*>(&h);
    lo = *reinterpret_cast<uint32_t*>(&l);
}

// ===========================================================================
// fused fp32 -> bf16 hi/lo split for all 8 source tensors (one launch)
// ===========================================================================
extern "C" __global__ void __launch_bounds__(256)
split_all(const float* __restrict__ q, const float* __restrict__ k,
          const float* __restrict__ v, const float* __restrict__ wq,
          const float* __restrict__ wk1, const float* __restrict__ wk2,
          const float* __restrict__ wv, const float* __restrict__ wo) {
    const float* src;
    __nv_bfloat16 *hi, *lo;
    int n4;
    switch (blockIdx.y) {
        case 0: src = q;   hi = in_q_h; lo = in_q_l; n4 = NELEM / 4; break;
        case 1: src = k;   hi = in_k_h; lo = in_k_l; n4 = NELEM / 4; break;
        case 2: src = v;   hi = in_v_h; lo = in_v_l; n4 = NELEM / 4; break;
        case 3: src = wq;  hi = w_h + 0 * (size_t)WSZ; lo = w_l + 0 * (size_t)WSZ; n4 = WSZ / 4; break;
        case 4: src = wk1; hi = w_h + 1 * (size_t)WSZ; lo = w_l + 1 * (size_t)WSZ; n4 = WSZ / 4; break;
        case 5: src = wk2; hi = w_h + 2 * (size_t)WSZ; lo = w_l + 2 * (size_t)WSZ; n4 = WSZ / 4; break;
        case 6: src = wv;  hi = w_h + 3 * (size_t)WSZ; lo = w_l + 3 * (size_t)WSZ; n4 = WSZ / 4; break;
        default: src = wo; hi = w_h + 4 * (size_t)WSZ; lo = w_l + 4 * (size_t)WSZ; n4 = WSZ / 4; break;
    }
    int i = blockIdx.x * 256 + threadIdx.x;
    if (i >= n4) return;
    float4 val = ((const float4*)src)[i];
    uint32_t h0, l0, h1, l1;
    split2(val.x, val.y, h0, l0);
    split2(val.z, val.w, h1, l1);
    ((uint32_t*)hi)[i * 2]     = h0;
    ((uint32_t*)hi)[i * 2 + 1] = h1;
    ((uint32_t*)lo)[i * 2]     = l0;
    ((uint32_t*)lo)[i * 2 + 1] = l1;
}

// ===========================================================================
// mma.sync GEMM: C[M,N] = A[M,K] @ W[N,K]^T + bias  (bf16 hi/lo, fp32 acc)
// CTA 128x128, K chunk 32, 256 threads (8 warps, 4m x 2n, warp tile 32x64).
// 3-stage cp.async pipeline, one barrier per K-chunk, warp-staggered slices
// (warps 0-3 do slice 0 then 1; warps 4-7 do 1 then 0) to break the
// LDSM/MMA phase convoy.
// nm: 0 = none, 1 = q (raw), 2 = k1 (scaled NSC1), 3 = k2 (scaled NSC2)
// ===========================================================================
#define GEMM_SMEM 98304

__device__ __forceinline__ void gemm_mma_body(
    const __nv_bfloat16* __restrict__ Ah, const __nv_bfloat16* __restrict__ Al,
    const __nv_bfloat16* __restrict__ Wh, const __nv_bfloat16* __restrict__ Wl,
    const float* __restrict__ bias, float* __restrict__ Cf,
    __nv_bfloat16* __restrict__ Ch, __nv_bfloat16* __restrict__ Cl,
    const int nm, float* __restrict__ Nout) {
    extern __shared__ char smem[];
    const uint32_t sbase = smem_u32(smem);
    const int tid = threadIdx.x;
    const int lane = tid & 31;
    const int wid = tid >> 5;
    const int bm = blockIdx.y * 128;
    const int bn = blockIdx.x * 128;
    const int wm = (wid & 3) * 32;
    const int wn = (wid >> 2) * 64;
    const int sw = (wid >> 2) & 1;      // slice-order stagger

    const int lr = tid >> 1;            // 0..127
    const int lg = (tid & 1) * 2;       // granule 0 or 2
    const size_t goffA = (size_t)(bm + lr) * E_DIM;
    const size_t goffW = (size_t)(bn + lr) * E_DIM;

    float acc[2][8][4];
#pragma unroll
    for (int mt = 0; mt < 2; mt++)
#pragma unroll
        for (int nt = 0; nt < 8; nt++)
#pragma unroll
            for (int e = 0; e < 4; e++) acc[mt][nt][e] = 0.0f;

#define LOAD_CHUNK(buf, kc) do {                                              \
    uint32_t dst0 = sbase + (buf) * 32768 + lr * 64;                          \
    _Pragma("unroll")                                                         \
    for (int j = 0; j < 2; j++) {                                             \
        int g = lg + j;                                                       \
        uint32_t d = dst0 + (((g) ^ ((lr >> 1) & 3)) << 4);                   \
        cp_async16(d,         Ah + goffA + (kc) + g * 8);                     \
        cp_async16(d + 8192,  Al + goffA + (kc) + g * 8);                     \
        cp_async16(d + 16384, Wh + goffW + (kc) + g * 8);                     \
        cp_async16(d + 24576, Wl + goffW + (kc) + g * 8);                     \
    }                                                                         \
} while (0)

    LOAD_CHUNK(0, 0);
    cp_commit();
    LOAD_CHUNK(1, 32);
    cp_commit();

    const int nk = E_DIM / 32;
    int stage = 0;
    for (int kc = 0; kc < nk; kc++) {
        cp_wait1();
        __syncthreads();
        if (kc + 2 < nk) {
            int ns = stage + 2; if (ns >= 3) ns -= 3;
            LOAD_CHUNK(ns, (kc + 2) * 32);
            cp_commit();
        }

        const uint32_t tb = sbase + stage * 32768;
#pragma unroll
        for (int si = 0; si < 2; si++) {
            const int s = si ^ sw;
            uint32_t a_h[2][4], a_l[2][4];
            const int ac = s * 2 + (lane >> 4);
#pragma unroll
            for (int mt = 0; mt < 2; mt++) {
                int r = wm + mt * 16 + (lane & 15);
                uint32_t ad = tb + r * 64 + ((ac ^ ((r >> 1) & 3)) << 4);
                ldsm4(ad, a_h[mt]);
                ldsm4(ad + 8192, a_l[mt]);
            }
            uint32_t b_h[8][2], b_l[8][2];
            const int grp = lane >> 3;
            const int bc = s * 2 + (grp & 1);
            const int br = wn + ((grp >> 1) << 3) + (lane & 7);
#pragma unroll
            for (int np = 0; np < 4; np++) {
                int r = br + np * 16;
                uint32_t bd = tb + 16384 + r * 64 + ((bc ^ ((r >> 1) & 3)) << 4);
                uint32_t qv[4];
                ldsm4(bd, qv);
                b_h[np * 2][0] = qv[0]; b_h[np * 2][1] = qv[1];
                b_h[np * 2 + 1][0] = qv[2]; b_h[np * 2 + 1][1] = qv[3];
                ldsm4(bd + 8192, qv);
                b_l[np * 2][0] = qv[0]; b_l[np * 2][1] = qv[1];
                b_l[np * 2 + 1][0] = qv[2]; b_l[np * 2 + 1][1] = qv[3];
            }
#pragma unroll
            for (int mt = 0; mt < 2; mt++)
#pragma unroll
                for (int nt = 0; nt < 8; nt++) {
                    mma16816(acc[mt][nt], a_h[mt], b_h[nt]);
                    mma16816(acc[mt][nt], a_h[mt], b_l[nt]);
                    mma16816(acc[mt][nt], a_l[mt], b_h[nt]);
                }
        }
        if (++stage >= 3) stage = 0;
    }
#undef LOAD_CHUNK

    // epilogue (+ fused per-row squared-norm when nm != 0)
    const float nsc = (nm == 1) ? 1.0f : (nm == 2 ? NSC1 : NSC2);
#pragma unroll
    for (int mt = 0; mt < 2; mt++) {
        int r0 = bm + wm + mt * 16 + (lane >> 2);
        float ns0 = 0.0f, ns1 = 0.0f;
#pragma unroll
        for (int nt = 0; nt < 8; nt++) {
            int cg = bn + wn + nt * 8 + ((lane & 3) << 1);
            float2 bb = *(const float2*)&bias[cg];
            float v00 = acc[mt][nt][0] + bb.x, v01 = acc[mt][nt][1] + bb.y;
            float v10 = acc[mt][nt][2] + bb.x, v11 = acc[mt][nt][3] + bb.y;
            if (nm) {
                ns0 = fmaf(v00, v00, ns0); ns0 = fmaf(v01, v01, ns0);
                ns1 = fmaf(v10, v10, ns1); ns1 = fmaf(v11, v11, ns1);
            }
            if (Cf) {
                *(float2*)&Cf[(size_t)r0 * E_DIM + cg] = make_float2(v00, v01);
                *(float2*)&Cf[(size_t)(r0 + 8) * E_DIM + cg] = make_float2(v10, v11);
            } else {
                uint32_t h0, l0, h1, l1;
                split2(v00, v01, h0, l0);
                split2(v10, v11, h1, l1);
                *(uint32_t*)&Ch[(size_t)r0 * E_DIM + cg] = h0;
                *(uint32_t*)&Cl[(size_t)r0 * E_DIM + cg] = l0;
                *(uint32_t*)&Ch[(size_t)(r0 + 8) * E_DIM + cg] = h1;
                *(uint32_t*)&Cl[(size_t)(r0 + 8) * E_DIM + cg] = l1;
            }
        }
        if (nm) {
            ns0 += __shfl_xor_sync(0xffffffffu, ns0, 1);
            ns0 += __shfl_xor_sync(0xffffffffu, ns0, 2);
            ns1 += __shfl_xor_sync(0xffffffffu, ns1, 1);
            ns1 += __shfl_xor_sync(0xffffffffu, ns1, 2);
            if ((lane & 3) == 0) {
                const int hh = (bn + wn) >> 6;
                const int bb_ = r0 & 3;
                const size_t nb = (size_t)(bb_ * 16 + hh) * 1024;
                Nout[nb + (r0 >> 2)] = ns0 * nsc;
                Nout[nb + (r0 >> 2) + 2] = ns1 * nsc;
            }
        }
    }
}

// Fused 4-way projection: z=0:q z=1:k1 z=2:k2 z=3:v  -> bf16 hi/lo outputs
extern "C" __global__ void __launch_bounds__(256, 2)
proj_kernel(const float* __restrict__ bias) {
    int z = blockIdx.z;
    if (z == 0)
        gemm_mma_body(in_q_h, in_q_l, w_h, w_l, bias, nullptr,
                      o_q_h, o_q_l, 1, n_q2);
    else if (z == 1)
        gemm_mma_body(in_k_h, in_k_l, w_h + (size_t)WSZ, w_l + (size_t)WSZ,
                      bias + E_DIM, nullptr, o_k1_h, o_k1_l, 2, n_k1);
    else if (z == 2)
        gemm_mma_body(in_k_h, in_k_l, w_h + 2 * (size_t)WSZ, w_l + 2 * (size_t)WSZ,
                      bias + 2 * E_DIM, nullptr, o_k2_h, o_k2_l, 3, n_k2);
    else
        gemm_mma_body(in_v_h, in_v_l, w_h + 3 * (size_t)WSZ, w_l + 3 * (size_t)WSZ,
                      bias + 3 * E_DIM, nullptr, o_v_h, o_v_l, 0, nullptr);
}

extern "C" __global__ void __launch_bounds__(256, 2)
out_kernel(const float* __restrict__ bias, float* __restrict__ C) {
    gemm_mma_body(ao_h, ao_l, w_h + (size_t)4 * WSZ, w_l + (size_t)4 * WSZ,
                  bias, C, nullptr, nullptr, 0, nullptr);
}

// ===========================================================================
// Tensorized Gaussian-kernel attention; Q frags + q2 in registers.
// Block = (64 q rows, bh), 256 threads = 8 warps (4 m-strips x 2 s-halves).
// QK passes warp-staggered: wn=0 does k1 then k2; wn=1 does k2 then k1.
// ===========================================================================
#define AT_ORED 0
#define AT_DEN  8704
#define AT_N    9216
#define AT_BUF0 10240
#define AT_BUFSZ 49152
#define AT_K1H 0
#define AT_K1L 8192
#define AT_K2H 16384
#define AT_K2L 24576
#define AT_VH  32768
#define AT_VL  40960
#define ATTN_SMEM (AT_BUF0 + 2 * AT_BUFSZ)

extern "C" __global__ void __launch_bounds__(256, 2)
attn_kernel(const float* __restrict__ pi) {
    extern __shared__ char smem[];
    const uint32_t sb = smem_u32(smem);
    const int tid = threadIdx.x;
    const int lane = tid & 31;
    const int wid = tid >> 5;
    const int wm = (wid & 3) * 16;
    const int wn = wid >> 2;
    const int qt = blockIdx.x;
    const int bh = blockIdx.y;
    const int b = bh >> 4;
    const int h = bh & 15;
    const int q0 = qt * 64;

    const float p1 = fminf(fmaxf(fabsf(pi[h]), 1e-6f), 2.0f);
    const float p2 = fminf(fmaxf(fabsf(pi[H_NUM + h]), 1e-6f), 2.0f);

    const int lr = tid >> 2;
    const int lc = (tid & 3) * 2;
    const size_t grow = (size_t)h * HD;

#define LOADKV(buf, s0) do {                                                      \
    uint32_t bdst = sb + AT_BUF0 + (buf) * AT_BUFSZ;                              \
    size_t gsrc = ((size_t)((s0) + lr) * B_SZ + b) * E_DIM + grow;                \
    _Pragma("unroll")                                                             \
    for (int j = 0; j < 2; j++) {                                                 \
        int c = lc + j;                                                           \
        uint32_t d = bdst + lr * 128 + ((c ^ (lr & 7)) << 4);                     \
        cp_async16(d + AT_K1H, o_k1_h + gsrc + c * 8);                            \
        cp_async16(d + AT_K1L, o_k1_l + gsrc + c * 8);                            \
        cp_async16(d + AT_K2H, o_k2_h + gsrc + c * 8);                            \
        cp_async16(d + AT_K2L, o_k2_l + gsrc + c * 8);                            \
        cp_async16(d + AT_VH,  o_v_h  + gsrc + c * 8);                            \
        cp_async16(d + AT_VL,  o_v_l  + gsrc + c * 8);                            \
    }                                                                             \
    if (tid < 16)                                                                 \
        cp_async16(sb + AT_N + (buf) * 512 + tid * 16,                            \
                   n_k1 + (size_t)bh * 1024 + (s0) + tid * 4);                    \
    else if (tid < 32)                                                            \
        cp_async16(sb + AT_N + (buf) * 512 + 256 + (tid - 16) * 16,               \
                   n_k2 + (size_t)bh * 1024 + (s0) + (tid - 16) * 4);             \
} while (0)

    // ---- Q fragments + q2 straight into registers ----
    uint32_t qfh[4][4], qfl[4][4];
    {
        const int ra = q0 + wm + (lane >> 2);
        const size_t qa = ((size_t)ra * B_SZ + b) * E_DIM + grow;
        const size_t qb = qa + (size_t)8 * B_SZ * E_DIM;
#pragma unroll
        for (int kk = 0; kk < 4; kk++) {
            const int c0 = kk * 16 + 2 * (lane & 3);
            qfh[kk][0] = *(const uint32_t*)&o_q_h[qa + c0];
            qfh[kk][1] = *(const uint32_t*)&o_q_h[qb + c0];
            qfh[kk][2] = *(const uint32_t*)&o_q_h[qa + c0 + 8];
            qfh[kk][3] = *(const uint32_t*)&o_q_h[qb + c0 + 8];
            qfl[kk][0] = *(const uint32_t*)&o_q_l[qa + c0];
            qfl[kk][1] = *(const uint32_t*)&o_q_l[qb + c0];
            qfl[kk][2] = *(const uint32_t*)&o_q_l[qa + c0 + 8];
            qfl[kk][3] = *(const uint32_t*)&o_q_l[qb + c0 + 8];
        }
    }
    const float q2a = n_q2[(size_t)bh * 1024 + q0 + wm + (lane >> 2)];
    const float q2b = n_q2[(size_t)bh * 1024 + q0 + wm + (lane >> 2) + 8];
    const float qc1a = NSC1 * q2a, qc2a = NSC2 * q2a;
    const float qc1b = NSC1 * q2b, qc2b = NSC2 * q2b;

    LOADKV(0, 0);
    cp_commit();

    float O[8][4];
#pragma unroll
    for (int nt = 0; nt < 8; nt++)
#pragma unroll
        for (int e = 0; e < 4; e++) O[nt][e] = 0.0f;
    float den0 = 0.0f, den1 = 0.0f;

    for (int st = 0; st < 16; st++) {
        cp_wait0();
        __syncthreads();
        if (st < 15) { LOADKV((st + 1) & 1, (st + 1) * 64); cp_commit(); }

        const uint32_t bb = sb + AT_BUF0 + (st & 1) * AT_BUFSZ;

        float S1[4][4], S2[4][4];
#pragma unroll
        for (int nt = 0; nt < 4; nt++)
#pragma unroll
            for (int e = 0; e < 4; e++) { S1[nt][e] = 0.0f; S2[nt][e] = 0.0f; }

        // ---- QK over this warp's 32-key half; pass order staggered by wn ----
#define QK_PASS(KOFF, S)                                                      \
        _Pragma("unroll")                                                     \
        for (int kk = 0; kk < 4; kk++) {                                      \
            const int grp = lane >> 3;                                        \
            const int c = kk * 2 + (grp & 1);                                 \
            const int rb = wn * 32 + ((grp >> 1) << 3) + (lane & 7);          \
            uint32_t bf[4][2], bl[4][2];                                      \
            _Pragma("unroll")                                                 \
            for (int np = 0; np < 2; np++) {                                  \
                int r = rb + np * 16;                                         \
                uint32_t ra = bb + r * 128 + ((c ^ (r & 7)) << 4);            \
                uint32_t qv[4];                                               \
                ldsm4(ra + (KOFF), qv);                                       \
                bf[np*2][0]=qv[0]; bf[np*2][1]=qv[1];                         \
                bf[np*2+1][0]=qv[2]; bf[np*2+1][1]=qv[3];                     \
                ldsm4(ra + (KOFF) + 8192, qv);                                \
                bl[np*2][0]=qv[0]; bl[np*2][1]=qv[1];                         \
                bl[np*2+1][0]=qv[2]; bl[np*2+1][1]=qv[3];                     \
            }                                                                 \
            _Pragma("unroll")                                                 \
            for (int nt = 0; nt < 4; nt++) {                                  \
                mma16816(S[nt], qfh[kk], bf[nt]);                             \
                mma16816(S[nt], qfh[kk], bl[nt]);                             \
                mma16816(S[nt], qfl[kk], bf[nt]);                             \
            }                                                                 \
        }

        if (wn == 0) {
            QK_PASS(AT_K1H, S1)
            QK_PASS(AT_K2H, S2)
        } else {
            QK_PASS(AT_K2H, S2)
            QK_PASS(AT_K1H, S1)
        }
#undef QK_PASS

        // ---- weights: w = p1*ex2(SC1*S1 + t1) + p2*ex2(SC2*S2 + t2) ----
        uint32_t wAh[2][4], wAl[2][4];
        {
            const float* k1p = (const float*)(smem + AT_N + (st & 1) * 512);
            const float* k2p = k1p + 64;
#pragma unroll
            for (int nt = 0; nt < 4; nt++) {
                const int cp0 = wn * 32 + nt * 8 + 2 * (lane & 3);
                const float k1a = k1p[cp0], k1b = k1p[cp0 + 1];
                const float k2a = k2p[cp0], k2b = k2p[cp0 + 1];
                const float t1aa = qc1a + k1a, t1ab = qc1a + k1b;
                const float t1ba = qc1b + k1a, t1bb = qc1b + k1b;
                const float t2aa = qc2a + k2a, t2ab = qc2a + k2b;
                const float t2ba = qc2b + k2a, t2bb = qc2b + k2b;
                float w00 = fmaf(p1, ex2f(fmaf(SC1, S1[nt][0], t1aa)),
                                 p2 * ex2f(fmaf(SC2, S2[nt][0], t2aa)));
                float w01 = fmaf(p1, ex2f(fmaf(SC1, S1[nt][1], t1ab)),
                                 p2 * ex2f(fmaf(SC2, S2[nt][1], t2ab)));
                float w10 = fmaf(p1, ex2f(fmaf(SC1, S1[nt][2], t1ba)),
                                 p2 * ex2f(fmaf(SC2, S2[nt][2], t2ba)));
                float w11 = fmaf(p1, ex2f(fmaf(SC1, S1[nt][3], t1bb)),
                                 p2 * ex2f(fmaf(SC2, S2[nt][3], t2bb)));
                den0 += w00 + w01;
                den1 += w10 + w11;
                uint32_t h0, l0, h1, l1;
                split2(w00, w01, h0, l0);
                split2(w10, w11, h1, l1);
                const int kk = nt >> 1;
                const int e = (nt & 1) * 2;
                wAh[kk][e]     = h0; wAl[kk][e]     = l0;
                wAh[kk][e + 1] = h1; wAl[kk][e + 1] = l1;
            }
        }

        // ---- AV: O(partial over s-half) += w @ V, all 64 cols ----
#pragma unroll
        for (int kk = 0; kk < 2; kk++) {
            uint32_t bvh[8][2], bvl[8][2];
            {
                int r = wn * 32 + kk * 16 + (lane & 15);
                uint32_t rowa = bb + AT_VH + r * 128;
                uint32_t rowb = bb + AT_VL + r * 128;
#pragma unroll
                for (int cb = 0; cb < 8; cb += 2) {
                    int g0 = cb + (lane >> 4);
                    uint32_t qv[4];
                    ldsm4t(rowa + ((g0 ^ (r & 7)) << 4), qv);
                    bvh[cb][0]=qv[0]; bvh[cb][1]=qv[1]; bvh[cb+1][0]=qv[2]; bvh[cb+1][1]=qv[3];
                    ldsm4t(rowb + ((g0 ^ (r & 7)) << 4), qv);
                    bvl[cb][0]=qv[0]; bvl[cb][1]=qv[1]; bvl[cb+1][0]=qv[2]; bvl[cb+1][1]=qv[3];
                }
            }
#pragma unroll
            for (int nt = 0; nt < 8; nt++) {
                mma16816(O[nt], wAh[kk], bvh[nt]);
                mma16816(O[nt], wAh[kk], bvl[nt]);
                mma16816(O[nt], wAl[kk], bvh[nt]);
            }
        }
    }
#undef LOADKV

    // ---- cross-warp reduction of O and den over the two s-halves ----
    den0 += __shfl_xor_sync(0xffffffffu, den0, 1);
    den0 += __shfl_xor_sync(0xffffffffu, den0, 2);
    den1 += __shfl_xor_sync(0xffffffffu, den1, 1);
    den1 += __shfl_xor_sync(0xffffffffu, den1, 2);

    float* dens = (float*)(smem + AT_DEN);
    float* ored = (float*)(smem + AT_ORED);   // pitch 34 floats, 64 rows
    const int r0 = wm + (lane >> 2);
    __syncthreads();
    if ((lane & 3) == 0) {
        dens[r0 * 2 + wn] = den0;
        dens[(r0 + 8) * 2 + wn] = den1;
    }
    // chunk 0: nt 0..3
    if (wn == 1) {
#pragma unroll
        for (int nt = 0; nt < 4; nt++) {
            const int c = nt * 8 + 2 * (lane & 3);
            *(float2*)&ored[r0 * 34 + c] = make_float2(O[nt][0], O[nt][1]);
            *(float2*)&ored[(r0 + 8) * 34 + c] = make_float2(O[nt][2], O[nt][3]);
        }
    }
    __syncthreads();
    float ia = 0.0f, ib = 0.0f;
    if (wn == 0) {
        ia = 1.0f / (dens[r0 * 2] + dens[r0 * 2 + 1] + 1e-6f);
        ib = 1.0f / (dens[(r0 + 8) * 2] + dens[(r0 + 8) * 2 + 1] + 1e-6f);
#pragma unroll
        for (int nt = 0; nt < 4; nt++) {
            const int c = nt * 8 + 2 * (lane & 3);
            float2 pa = *(const float2*)&ored[r0 * 34 + c];
            float2 pb = *(const float2*)&ored[(r0 + 8) * 34 + c];
            float o00 = (O[nt][0] + pa.x) * ia, o01 = (O[nt][1] + pa.y) * ia;
            float o10 = (O[nt][2] + pb.x) * ib, o11 = (O[nt][3] + pb.y) * ib;
            uint32_t h0, l0, h1, l1;
            split2(o00, o01, h0, l0);
            split2(o10, o11, h1, l1);
            size_t i0 = ((size_t)(q0 + r0) * B_SZ + b) * E_DIM + grow + c;
            size_t i1 = i0 + (size_t)8 * B_SZ * E_DIM;
            *(uint32_t*)&ao_h[i0] = h0; *(uint32_t*)&ao_l[i0] = l0;
            *(uint32_t*)&ao_h[i1] = h1; *(uint32_t*)&ao_l[i1] = l1;
        }
    }
    __syncthreads();
    // chunk 1: nt 4..7
    if (wn == 1) {
#pragma unroll
        for (int nt = 4; nt < 8; nt++) {
            const int c = (nt - 4) * 8 + 2 * (lane & 3);
            *(float2*)&ored[r0 * 34 + c] = make_float2(O[nt][0], O[nt][1]);
            *(float2*)&ored[(r0 + 8) * 34 + c] = make_float2(O[nt][2], O[nt][3]);
        }
    }
    __syncthreads();
    if (wn == 0) {
#pragma unroll
        for (int nt = 4; nt < 8; nt++) {
            const int c = (nt - 4) * 8 + 2 * (lane & 3);
            float2 pa = *(const float2*)&ored[r0 * 34 + c];
            float2 pb = *(const float2*)&ored[(r0 + 8) * 34 + c];
            float o00 = (O[nt][0] + pa.x) * ia, o01 = (O[nt][1] + pa.y) * ia;
            float o10 = (O[nt][2] + pb.x) * ib, o11 = (O[nt][3] + pb.y) * ib;
            uint32_t h0, l0, h1, l1;
            split2(o00, o01, h0, l0);
            split2(o10, o11, h1, l1);
            const int cg = nt * 8 + 2 * (lane & 3);
            size_t i0 = ((size_t)(q0 + r0) * B_SZ + b) * E_DIM + grow + cg;
            size_t i1 = i0 + (size_t)8 * B_SZ * E_DIM;
            *(uint32_t*)&ao_h[i0] = h0; *(uint32_t*)&ao_l[i0] = l0;
            *(uint32_t*)&ao_h[i1] = h1; *(uint32_t*)&ao_l[i1] = l1;
        }
    }
}

// ---------------------------------------------------------------------------
extern "C" void kernel_launch(void* const* d_in, const int* in_sizes, int n_in,
                              void* d_out, int out_size) {
    const float* query = (const float*)d_in[0];
    const float* key   = (const float*)d_in[1];
    const float* value = (const float*)d_in[2];
    const float* wq    = (const float*)d_in[3];
    const float* wk1   = (const float*)d_in[4];
    const float* wk2   = (const float*)d_in[5];
    const float* wv    = (const float*)d_in[6];
    const float* bias  = (const float*)d_in[7];
    const float* wo    = (const float*)d_in[8];
    const float* bo    = (const float*)d_in[9];
    const float* pi    = (const float*)d_in[10];
    float* out = (float*)d_out;

    cudaFuncSetAttribute(proj_kernel,
                         cudaFuncAttributeMaxDynamicSharedMemorySize, GEMM_SMEM);
    cudaFuncSetAttribute(out_kernel,
                         cudaFuncAttributeMaxDynamicSharedMemorySize, GEMM_SMEM);
    cudaFuncSetAttribute(attn_kernel,
                         cudaFuncAttributeMaxDynamicSharedMemorySize, ATTN_SMEM);

    dim3 gsplit(4096, 8);
    split_all<<<gsplit, 256>>>(query, key, value, wq, wk1, wk2, wv, wo);

    dim3 gproj(8, 32, 4);
    proj_kernel<<<gproj, 256, GEMM_SMEM>>>(bias);

    dim3 gattn(16, 64);
    attn_kernel<<<gattn, 256, ATTN_SMEM>>>(pi);

    dim3 gout(8, 32);
    out_kernel<<<gout, 256, GEMM_SMEM>>>(bo, out);
}

// round 16
// speedup vs baseline: 2.2539x; 2.2539x over previous
#include <cuda_runtime.h>
#include <cuda_fp16.h>
#include <math.h>
#include <cstdint>

#define E_DIM 1024
#define M_DIM 4096
#define H_NUM 16
#define HD 64
#define B_SZ 4
#define NELEM (M_DIM * E_DIM)
#define WSZ (E_DIM * E_DIM)

// exp(-c*d) = exp2(-c*log2e*d).  c1=1/16, c2=3/16.
#define NSC1 (-0.09016844005555976f)   // -c1*log2e
#define NSC2 (-0.27050532016667927f)   // -c2*log2e
#define SC1  (0.18033688011111952f)    // +2*c1*log2e
#define SC2  (0.54101064033335854f)    // +2*c2*log2e

// fp16 buffers
__device__ __half in_q[NELEM];
__device__ __half in_k[NELEM];
__device__ __half in_v[NELEM];
__device__ __half w_f[5 * WSZ];

__device__ __half o_q[NELEM];
__device__ __half o_k1[NELEM];
__device__ __half o_k2[NELEM];
__device__ __half o_v[NELEM];
__device__ __half ao_f[NELEM];

// norms: [bh*1024 + t].  n_q2 raw q^2 (from rounded fp16 values);
// n_k1/n_k2 pre-scaled by NSC1/NSC2 (from rounded fp16 values).
__device__ float n_q2[64 * 1024];
__device__ float n_k1[64 * 1024];
__device__ float n_k2[64 * 1024];

// ===========================================================================
// helpers
// ===========================================================================
__device__ __forceinline__ uint32_t smem_u32(const void* p) {
    uint32_t a;
    asm("{ .reg .u64 t; cvta.to.shared.u64 t, %1; cvt.u32.u64 %0, t; }"
        : "=r"(a) : "l"(p));
    return a;
}
__device__ __forceinline__ void cp_async16(uint32_t dst, const void* src) {
    asm volatile("cp.async.cg.shared.global [%0], [%1], 16;"
                 :: "r"(dst), "l"(src));
}
__device__ __forceinline__ void cp_commit() {
    asm volatile("cp.async.commit_group;" ::: "memory");
}
__device__ __forceinline__ void cp_wait1() {
    asm volatile("cp.async.wait_group 1;" ::: "memory");
}
__device__ __forceinline__ void cp_wait0() {
    asm volatile("cp.async.wait_group 0;" ::: "memory");
}
__device__ __forceinline__ void ldsm4(uint32_t addr, uint32_t* r) {
    asm volatile("ldmatrix.sync.aligned.m8n8.x4.shared.b16 {%0,%1,%2,%3}, [%4];"
                 : "=r"(r[0]), "=r"(r[1]), "=r"(r[2]), "=r"(r[3]) : "r"(addr));
}
__device__ __forceinline__ void ldsm4t(uint32_t addr, uint32_t* r) {
    asm volatile("ldmatrix.sync.aligned.m8n8.x4.trans.shared.b16 {%0,%1,%2,%3}, [%4];"
                 : "=r"(r[0]), "=r"(r[1]), "=r"(r[2]), "=r"(r[3]) : "r"(addr));
}
__device__ __forceinline__ void mma16816(float* d, const uint32_t* a,
                                         const uint32_t* b) {
    asm volatile(
        "mma.sync.aligned.m16n8k16.row.col.f32.f16.f16.f32 "
        "{%0,%1,%2,%3}, {%4,%5,%6,%7}, {%8,%9}, {%0,%1,%2,%3};"
        : "+f"(d[0]), "+f"(d[1]), "+f"(d[2]), "+f"(d[3])
        : "r"(a[0]), "r"(a[1]), "r"(a[2]), "r"(a[3]), "r"(b[0]), "r"(b[1]));
}
__device__ __forceinline__ float ex2f(float x) {
    float y;
    asm("ex2.approx.ftz.f32 %0, %1;" : "=f"(y) : "f"(x));
    return y;
}
__device__ __forceinline__ uint32_t pk_h2(float x, float y) {
    __half2 h = __float22half2_rn(make_float2(x, y));
    return *reinterpret_cast<uint32_t*>(&h);
}
__device__ __forceinline__ float2 unpk_h2(uint32_t u) {
    __half2 h = *reinterpret_cast<__half2*>(&u);
    return __half22float2(h);
}

// ===========================================================================
// fused fp32 -> fp16 convert for all 8 source tensors (one launch)
// ===========================================================================
extern "C" __global__ void __launch_bounds__(256)
split_all(const float* __restrict__ q, const float* __restrict__ k,
          const float* __restrict__ v, const float* __restrict__ wq,
          const float* __restrict__ wk1, const float* __restrict__ wk2,
          const float* __restrict__ wv, const float* __restrict__ wo) {
    const float* src;
    __half* dst;
    int n4;
    switch (blockIdx.y) {
        case 0: src = q;   dst = in_q; n4 = NELEM / 4; break;
        case 1: src = k;   dst = in_k; n4 = NELEM / 4; break;
        case 2: src = v;   dst = in_v; n4 = NELEM / 4; break;
        case 3: src = wq;  dst = w_f + 0 * (size_t)WSZ; n4 = WSZ / 4; break;
        case 4: src = wk1; dst = w_f + 1 * (size_t)WSZ; n4 = WSZ / 4; break;
        case 5: src = wk2; dst = w_f + 2 * (size_t)WSZ; n4 = WSZ / 4; break;
        case 6: src = wv;  dst = w_f + 3 * (size_t)WSZ; n4 = WSZ / 4; break;
        default: src = wo; dst = w_f + 4 * (size_t)WSZ; n4 = WSZ / 4; break;
    }
    int i = blockIdx.x * 256 + threadIdx.x;
    if (i >= n4) return;
    float4 val = ((const float4*)src)[i];
    uint2 o;
    o.x = pk_h2(val.x, val.y);
    o.y = pk_h2(val.z, val.w);
    ((uint2*)dst)[i] = o;
}

// ===========================================================================
// mma.sync GEMM: C[M,N] = A[M,K] @ W[N,K]^T + bias  (fp16 single product)
// CTA 128x128, K chunk 32, 256 threads (8 warps, 4m x 2n, warp tile 32x64).
// 3-stage cp.async pipeline, one barrier per K-chunk. smem 48KB, 2 CTA/SM.
// nm: 0 = none, 1 = q (raw), 2 = k1 (scaled NSC1), 3 = k2 (scaled NSC2)
// Norms computed from the fp16-ROUNDED outputs for dist consistency.
// ===========================================================================
#define GEMM_SMEM 49152

__device__ __forceinline__ void gemm_mma_body(
    const __half* __restrict__ A, const __half* __restrict__ W,
    const float* __restrict__ bias, float* __restrict__ Cf,
    __half* __restrict__ Ch, const int nm, float* __restrict__ Nout) {
    extern __shared__ char smem[];
    const uint32_t sbase = smem_u32(smem);
    const int tid = threadIdx.x;
    const int lane = tid & 31;
    const int wid = tid >> 5;
    const int bm = blockIdx.y * 128;
    const int bn = blockIdx.x * 128;
    const int wm = (wid & 3) * 32;
    const int wn = (wid >> 2) * 64;

    const int lr = tid >> 1;            // 0..127
    const int lg = (tid & 1) * 2;       // granule 0 or 2
    const size_t goffA = (size_t)(bm + lr) * E_DIM;
    const size_t goffW = (size_t)(bn + lr) * E_DIM;

    float acc[2][8][4];
#pragma unroll
    for (int mt = 0; mt < 2; mt++)
#pragma unroll
        for (int nt = 0; nt < 8; nt++)
#pragma unroll
            for (int e = 0; e < 4; e++) acc[mt][nt][e] = 0.0f;

#define LOAD_CHUNK(buf, kc) do {                                              \
    uint32_t dst0 = sbase + (buf) * 16384 + lr * 64;                          \
    _Pragma("unroll")                                                         \
    for (int j = 0; j < 2; j++) {                                             \
        int g = lg + j;                                                       \
        uint32_t d = dst0 + (((g) ^ ((lr >> 1) & 3)) << 4);                   \
        cp_async16(d,        A + goffA + (kc) + g * 8);                       \
        cp_async16(d + 8192, W + goffW + (kc) + g * 8);                       \
    }                                                                         \
} while (0)

    LOAD_CHUNK(0, 0);
    cp_commit();
    LOAD_CHUNK(1, 32);
    cp_commit();

    const int nk = E_DIM / 32;
    int stage = 0;
    for (int kc = 0; kc < nk; kc++) {
        cp_wait1();
        __syncthreads();
        if (kc + 2 < nk) {
            int ns = stage + 2; if (ns >= 3) ns -= 3;
            LOAD_CHUNK(ns, (kc + 2) * 32);
            cp_commit();
        }

        const uint32_t tb = sbase + stage * 16384;
#pragma unroll
        for (int s = 0; s < 2; s++) {
            uint32_t a_f[2][4];
            const int ac = s * 2 + (lane >> 4);
#pragma unroll
            for (int mt = 0; mt < 2; mt++) {
                int r = wm + mt * 16 + (lane & 15);
                uint32_t ad = tb + r * 64 + ((ac ^ ((r >> 1) & 3)) << 4);
                ldsm4(ad, a_f[mt]);
            }
            uint32_t b_f[8][2];
            const int grp = lane >> 3;
            const int bc = s * 2 + (grp & 1);
            const int br = wn + ((grp >> 1) << 3) + (lane & 7);
#pragma unroll
            for (int np = 0; np < 4; np++) {
                int r = br + np * 16;
                uint32_t bd = tb + 8192 + r * 64 + ((bc ^ ((r >> 1) & 3)) << 4);
                uint32_t qv[4];
                ldsm4(bd, qv);
                b_f[np * 2][0] = qv[0]; b_f[np * 2][1] = qv[1];
                b_f[np * 2 + 1][0] = qv[2]; b_f[np * 2 + 1][1] = qv[3];
            }
#pragma unroll
            for (int mt = 0; mt < 2; mt++)
#pragma unroll
                for (int nt = 0; nt < 8; nt++)
                    mma16816(acc[mt][nt], a_f[mt], b_f[nt]);
        }
        if (++stage >= 3) stage = 0;
    }
#undef LOAD_CHUNK

    // epilogue: fp16 (or fp32) store + norms from ROUNDED values
    const float nsc = (nm == 1) ? 1.0f : (nm == 2 ? NSC1 : NSC2);
#pragma unroll
    for (int mt = 0; mt < 2; mt++) {
        int r0 = bm + wm + mt * 16 + (lane >> 2);
        float ns0 = 0.0f, ns1 = 0.0f;
#pragma unroll
        for (int nt = 0; nt < 8; nt++) {
            int cg = bn + wn + nt * 8 + ((lane & 3) << 1);
            float2 bb = *(const float2*)&bias[cg];
            float v00 = acc[mt][nt][0] + bb.x, v01 = acc[mt][nt][1] + bb.y;
            float v10 = acc[mt][nt][2] + bb.x, v11 = acc[mt][nt][3] + bb.y;
            if (Cf) {
                *(float2*)&Cf[(size_t)r0 * E_DIM + cg] = make_float2(v00, v01);
                *(float2*)&Cf[(size_t)(r0 + 8) * E_DIM + cg] = make_float2(v10, v11);
            } else {
                uint32_t p0 = pk_h2(v00, v01);
                uint32_t p1 = pk_h2(v10, v11);
                *(uint32_t*)&Ch[(size_t)r0 * E_DIM + cg] = p0;
                *(uint32_t*)&Ch[(size_t)(r0 + 8) * E_DIM + cg] = p1;
                if (nm) {
                    float2 f0 = unpk_h2(p0);
                    float2 f1 = unpk_h2(p1);
                    ns0 = fmaf(f0.x, f0.x, ns0); ns0 = fmaf(f0.y, f0.y, ns0);
                    ns1 = fmaf(f1.x, f1.x, ns1); ns1 = fmaf(f1.y, f1.y, ns1);
                }
            }
        }
        if (nm) {
            ns0 += __shfl_xor_sync(0xffffffffu, ns0, 1);
            ns0 += __shfl_xor_sync(0xffffffffu, ns0, 2);
            ns1 += __shfl_xor_sync(0xffffffffu, ns1, 1);
            ns1 += __shfl_xor_sync(0xffffffffu, ns1, 2);
            if ((lane & 3) == 0) {
                const int hh = (bn + wn) >> 6;
                const int bb_ = r0 & 3;
                const size_t nb = (size_t)(bb_ * 16 + hh) * 1024;
                Nout[nb + (r0 >> 2)] = ns0 * nsc;
                Nout[nb + (r0 >> 2) + 2] = ns1 * nsc;
            }
        }
    }
}

// Fused 4-way projection: z=0:q z=1:k1 z=2:k2 z=3:v  -> fp16 outputs + norms
extern "C" __global__ void __launch_bounds__(256, 2)
proj_kernel(const float* __restrict__ bias) {
    int z = blockIdx.z;
    if (z == 0)
        gemm_mma_body(in_q, w_f, bias, nullptr, o_q, 1, n_q2);
    else if (z == 1)
        gemm_mma_body(in_k, w_f + (size_t)WSZ, bias + E_DIM, nullptr,
                      o_k1, 2, n_k1);
    else if (z == 2)
        gemm_mma_body(in_k, w_f + 2 * (size_t)WSZ, bias + 2 * E_DIM, nullptr,
                      o_k2, 3, n_k2);
    else
        gemm_mma_body(in_v, w_f + 3 * (size_t)WSZ, bias + 3 * E_DIM, nullptr,
                      o_v, 0, nullptr);
}

extern "C" __global__ void __launch_bounds__(256, 2)
out_kernel(const float* __restrict__ bias, float* __restrict__ C) {
    gemm_mma_body(ao_f, w_f + (size_t)4 * WSZ, bias, C, nullptr, 0, nullptr);
}

// ===========================================================================
// Tensorized Gaussian-kernel attention (fp16 single product).
// Block = (64 q rows, bh), 256 threads = 8 warps (4 m-strips x 2 s-halves).
// ===========================================================================
#define AT_ORED 0
#define AT_DEN  8704
#define AT_BUF0 9216
#define AT_BUFSZ 25088
#define AT_K1 0
#define AT_K2 8192
#define AT_V  16384
#define AT_N1 24576
#define AT_N2 24832
#define ATTN_SMEM (AT_BUF0 + 2 * AT_BUFSZ)

extern "C" __global__ void __launch_bounds__(256, 2)
attn_kernel(const float* __restrict__ pi) {
    extern __shared__ char smem[];
    const uint32_t sb = smem_u32(smem);
    const int tid = threadIdx.x;
    const int lane = tid & 31;
    const int wid = tid >> 5;
    const int wm = (wid & 3) * 16;
    const int wn = wid >> 2;
    const int qt = blockIdx.x;
    const int bh = blockIdx.y;
    const int b = bh >> 4;
    const int h = bh & 15;
    const int q0 = qt * 64;

    const float p1 = fminf(fmaxf(fabsf(pi[h]), 1e-6f), 2.0f);
    const float p2 = fminf(fmaxf(fabsf(pi[H_NUM + h]), 1e-6f), 2.0f);

    const int lr = tid >> 2;
    const int lc = (tid & 3) * 2;
    const size_t grow = (size_t)h * HD;

#define LOADKV(buf, s0) do {                                                      \
    uint32_t bdst = sb + AT_BUF0 + (buf) * AT_BUFSZ;                              \
    size_t gsrc = ((size_t)((s0) + lr) * B_SZ + b) * E_DIM + grow;                \
    _Pragma("unroll")                                                             \
    for (int j = 0; j < 2; j++) {                                                 \
        int c = lc + j;                                                           \
        uint32_t d = bdst + lr * 128 + ((c ^ (lr & 7)) << 4);                     \
        cp_async16(d + AT_K1, o_k1 + gsrc + c * 8);                               \
        cp_async16(d + AT_K2, o_k2 + gsrc + c * 8);                               \
        cp_async16(d + AT_V,  o_v  + gsrc + c * 8);                               \
    }                                                                             \
    if (tid < 16)                                                                 \
        cp_async16(bdst + AT_N1 + tid * 16,                                       \
                   n_k1 + (size_t)bh * 1024 + (s0) + tid * 4);                    \
    else if (tid < 32)                                                            \
        cp_async16(bdst + AT_N2 + (tid - 16) * 16,                                \
                   n_k2 + (size_t)bh * 1024 + (s0) + (tid - 16) * 4);             \
} while (0)

    // ---- Q fragments + q2 straight into registers ----
    uint32_t qf[4][4];
    {
        const int ra = q0 + wm + (lane >> 2);
        const size_t qa = ((size_t)ra * B_SZ + b) * E_DIM + grow;
        const size_t qb = qa + (size_t)8 * B_SZ * E_DIM;
#pragma unroll
        for (int kk = 0; kk < 4; kk++) {
            const int c0 = kk * 16 + 2 * (lane & 3);
            qf[kk][0] = *(const uint32_t*)&o_q[qa + c0];
            qf[kk][1] = *(const uint32_t*)&o_q[qb + c0];
            qf[kk][2] = *(const uint32_t*)&o_q[qa + c0 + 8];
            qf[kk][3] = *(const uint32_t*)&o_q[qb + c0 + 8];
        }
    }
    const float q2a = n_q2[(size_t)bh * 1024 + q0 + wm + (lane >> 2)];
    const float q2b = n_q2[(size_t)bh * 1024 + q0 + wm + (lane >> 2) + 8];
    const float qc1a = NSC1 * q2a, qc2a = NSC2 * q2a;
    const float qc1b = NSC1 * q2b, qc2b = NSC2 * q2b;

    LOADKV(0, 0);
    cp_commit();

    float O[8][4];
#pragma unroll
    for (int nt = 0; nt < 8; nt++)
#pragma unroll
        for (int e = 0; e < 4; e++) O[nt][e] = 0.0f;
    float den0 = 0.0f, den1 = 0.0f;

    for (int st = 0; st < 16; st++) {
        cp_wait0();
        __syncthreads();
        if (st < 15) { LOADKV((st + 1) & 1, (st + 1) * 64); cp_commit(); }

        const uint32_t bb = sb + AT_BUF0 + (st & 1) * AT_BUFSZ;
        char* bbp = smem + AT_BUF0 + (st & 1) * AT_BUFSZ;

        float S1[4][4], S2[4][4];
#pragma unroll
        for (int nt = 0; nt < 4; nt++)
#pragma unroll
            for (int e = 0; e < 4; e++) { S1[nt][e] = 0.0f; S2[nt][e] = 0.0f; }

        // ---- QK over this warp's 32-key half ----
#pragma unroll
        for (int kk = 0; kk < 4; kk++) {
            const int grp = lane >> 3;
            const int c = kk * 2 + (grp & 1);
            const int rb = wn * 32 + ((grp >> 1) << 3) + (lane & 7);
            uint32_t b1[4][2], b2[4][2];
#pragma unroll
            for (int np = 0; np < 2; np++) {
                int r = rb + np * 16;
                uint32_t ra = bb + r * 128 + ((c ^ (r & 7)) << 4);
                uint32_t qv[4];
                ldsm4(ra + AT_K1, qv);
                b1[np*2][0]=qv[0]; b1[np*2][1]=qv[1];
                b1[np*2+1][0]=qv[2]; b1[np*2+1][1]=qv[3];
                ldsm4(ra + AT_K2, qv);
                b2[np*2][0]=qv[0]; b2[np*2][1]=qv[1];
                b2[np*2+1][0]=qv[2]; b2[np*2+1][1]=qv[3];
            }
#pragma unroll
            for (int nt = 0; nt < 4; nt++) {
                mma16816(S1[nt], qf[kk], b1[nt]);
                mma16816(S2[nt], qf[kk], b2[nt]);
            }
        }

        // ---- weights: w = p1*ex2(SC1*S1 + t1) + p2*ex2(SC2*S2 + t2) ----
        uint32_t wA[2][4];
        {
            const float* k1p = (const float*)(bbp + AT_N1);
            const float* k2p = (const float*)(bbp + AT_N2);
#pragma unroll
            for (int nt = 0; nt < 4; nt++) {
                const int cp0 = wn * 32 + nt * 8 + 2 * (lane & 3);
                const float k1a = k1p[cp0], k1b = k1p[cp0 + 1];
                const float k2a = k2p[cp0], k2b = k2p[cp0 + 1];
                float w00 = fmaf(p1, ex2f(fmaf(SC1, S1[nt][0], qc1a + k1a)),
                                 p2 * ex2f(fmaf(SC2, S2[nt][0], qc2a + k2a)));
                float w01 = fmaf(p1, ex2f(fmaf(SC1, S1[nt][1], qc1a + k1b)),
                                 p2 * ex2f(fmaf(SC2, S2[nt][1], qc2a + k2b)));
                float w10 = fmaf(p1, ex2f(fmaf(SC1, S1[nt][2], qc1b + k1a)),
                                 p2 * ex2f(fmaf(SC2, S2[nt][2], qc2b + k2a)));
                float w11 = fmaf(p1, ex2f(fmaf(SC1, S1[nt][3], qc1b + k1b)),
                                 p2 * ex2f(fmaf(SC2, S2[nt][3], qc2b + k2b)));
                // round to fp16 first; accumulate den from the ROUNDED values
                uint32_t h0 = pk_h2(w00, w01);
                uint32_t h1 = pk_h2(w10, w11);
                float2 r0f = unpk_h2(h0);
                float2 r1f = unpk_h2(h1);
                den0 += r0f.x + r0f.y;
                den1 += r1f.x + r1f.y;
                const int kk = nt >> 1;
                const int e = (nt & 1) * 2;
                wA[kk][e]     = h0;
                wA[kk][e + 1] = h1;
            }
        }

        // ---- AV: O(partial over s-half) += w @ V, all 64 cols ----
#pragma unroll
        for (int kk = 0; kk < 2; kk++) {
            uint32_t bv[8][2];
            {
                int r = wn * 32 + kk * 16 + (lane & 15);
                uint32_t rowa = bb + AT_V + r * 128;
#pragma unroll
                for (int cb = 0; cb < 8; cb += 2) {
                    int g0 = cb + (lane >> 4);
                    uint32_t qv[4];
                    ldsm4t(rowa + ((g0 ^ (r & 7)) << 4), qv);
                    bv[cb][0]=qv[0]; bv[cb][1]=qv[1];
                    bv[cb+1][0]=qv[2]; bv[cb+1][1]=qv[3];
                }
            }
#pragma unroll
            for (int nt = 0; nt < 8; nt++)
                mma16816(O[nt], wA[kk], bv[nt]);
        }
    }
#undef LOADKV

    // ---- cross-warp reduction of O and den over the two s-halves ----
    den0 += __shfl_xor_sync(0xffffffffu, den0, 1);
    den0 += __shfl_xor_sync(0xffffffffu, den0, 2);
    den1 += __shfl_xor_sync(0xffffffffu, den1, 1);
    den1 += __shfl_xor_sync(0xffffffffu, den1, 2);

    float* dens = (float*)(smem + AT_DEN);
    float* ored = (float*)(smem + AT_ORED);   // pitch 34 floats, 64 rows
    const int r0 = wm + (lane >> 2);
    __syncthreads();
    if ((lane & 3) == 0) {
        dens[r0 * 2 + wn] = den0;
        dens[(r0 + 8) * 2 + wn] = den1;
    }
    // chunk 0: nt 0..3
    if (wn == 1) {
#pragma unroll
        for (int nt = 0; nt < 4; nt++) {
            const int c = nt * 8 + 2 * (lane & 3);
            *(float2*)&ored[r0 * 34 + c] = make_float2(O[nt][0], O[nt][1]);
            *(float2*)&ored[(r0 + 8) * 34 + c] = make_float2(O[nt][2], O[nt][3]);
        }
    }
    __syncthreads();
    float ia = 0.0f, ib = 0.0f;
    if (wn == 0) {
        ia = 1.0f / (dens[r0 * 2] + dens[r0 * 2 + 1] + 1e-6f);
        ib = 1.0f / (dens[(r0 + 8) * 2] + dens[(r0 + 8) * 2 + 1] + 1e-6f);
#pragma unroll
        for (int nt = 0; nt < 4; nt++) {
            const int c = nt * 8 + 2 * (lane & 3);
            float2 pa = *(const float2*)&ored[r0 * 34 + c];
            float2 pb = *(const float2*)&ored[(r0 + 8) * 34 + c];
            uint32_t h0 = pk_h2((O[nt][0] + pa.x) * ia, (O[nt][1] + pa.y) * ia);
            uint32_t h1 = pk_h2((O[nt][2] + pb.x) * ib, (O[nt][3] + pb.y) * ib);
            size_t i0 = ((size_t)(q0 + r0) * B_SZ + b) * E_DIM + grow + c;
            size_t i1 = i0 + (size_t)8 * B_SZ * E_DIM;
            *(uint32_t*)&ao_f[i0] = h0;
            *(uint32_t*)&ao_f[i1] = h1;
        }
    }
    __syncthreads();
    // chunk 1: nt 4..7
    if (wn == 1) {
#pragma unroll
        for (int nt = 4; nt < 8; nt++) {
            const int c = (nt - 4) * 8 + 2 * (lane & 3);
            *(float2*)&ored[r0 * 34 + c] = make_float2(O[nt][0], O[nt][1]);
            *(float2*)&ored[(r0 + 8) * 34 + c] = make_float2(O[nt][2], O[nt][3]);
        }
    }
    __syncthreads();
    if (wn == 0) {
#pragma unroll
        for (int nt = 4; nt < 8; nt++) {
            const int c = (nt - 4) * 8 + 2 * (lane & 3);
            float2 pa = *(const float2*)&ored[r0 * 34 + c];
            float2 pb = *(const float2*)&ored[(r0 + 8) * 34 + c];
            uint32_t h0 = pk_h2((O[nt][0] + pa.x) * ia, (O[nt][1] + pa.y) * ia);
            uint32_t h1 = pk_h2((O[nt][2] + pb.x) * ib, (O[nt][3] + pb.y) * ib);
            const int cg = nt * 8 + 2 * (lane & 3);
            size_t i0 = ((size_t)(q0 + r0) * B_SZ + b) * E_DIM + grow + cg;
            size_t i1 = i0 + (size_t)8 * B_SZ * E_DIM;
            *(uint32_t*)&ao_f[i0] = h0;
            *(uint32_t*)&ao_f[i1] = h1;
        }
    }
}

// ---------------------------------------------------------------------------
extern "C" void kernel_launch(void* const* d_in, const int* in_sizes, int n_in,
                              void* d_out, int out_size) {
    const float* query = (const float*)d_in[0];
    const float* key   = (const float*)d_in[1];
    const float* value = (const float*)d_in[2];
    const float* wq    = (const float*)d_in[3];
    const float* wk1   = (const float*)d_in[4];
    const float* wk2   = (const float*)d_in[5];
    const float* wv    = (const float*)d_in[6];
    const float* bias  = (const float*)d_in[7];
    const float* wo    = (const float*)d_in[8];
    const float* bo    = (const float*)d_in[9];
    const float* pi    = (const float*)d_in[10];
    float* out = (float*)d_out;

    cudaFuncSetAttribute(proj_kernel,
                         cudaFuncAttributeMaxDynamicSharedMemorySize, GEMM_SMEM);
    cudaFuncSetAttribute(out_kernel,
                         cudaFuncAttributeMaxDynamicSharedMemorySize, GEMM_SMEM);
    cudaFuncSetAttribute(attn_kernel,
                         cudaFuncAttributeMaxDynamicSharedMemorySize, ATTN_SMEM);

    dim3 gsplit(4096, 8);
    split_all<<<gsplit, 256>>>(query, key, value, wq, wk1, wk2, wv, wo);

    dim3 gproj(8, 32, 4);
    proj_kernel<<<gproj, 256, GEMM_SMEM>>>(bias);

    dim3 gattn(16, 64);
    attn_kernel<<<gattn, 256, ATTN_SMEM>>>(pi);

    dim3 gout(8, 32);
    out_kernel<<<gout, 256, GEMM_SMEM>>>(bo, out);
}

// round 17
// speedup vs baseline: 2.3609x; 1.0475x over previous
#include <cuda_runtime.h>
#include <cuda_fp16.h>
#include <math.h>
#include <cstdint>

#define E_DIM 1024
#define M_DIM 4096
#define H_NUM 16
#define HD 64
#define B_SZ 4
#define NELEM (M_DIM * E_DIM)
#define WSZ (E_DIM * E_DIM)

// exp(-c*d) = exp2(-c*log2e*d).  c1=1/16, c2=3/16.
#define NSC1 (-0.09016844005555976f)   // -c1*log2e
#define NSC2 (-0.27050532016667927f)   // -c2*log2e
#define SC1  (0.18033688011111952f)    // +2*c1*log2e
#define SC2  (0.54101064033335854f)    // +2*c2*log2e

// fp16 buffers
__device__ __half in_q[NELEM];
__device__ __half in_k[NELEM];
__device__ __half in_v[NELEM];
__device__ __half w_f[5 * WSZ];

__device__ __half o_q[NELEM];
__device__ __half o_k1[NELEM];
__device__ __half o_k2[NELEM];
__device__ __half o_v[NELEM];
__device__ __half ao_f[NELEM];

// norms: [bh*1024 + t].  n_q2 raw q^2 (from rounded fp16 values);
// n_k1/n_k2 pre-scaled by NSC1/NSC2 (from rounded fp16 values).
__device__ float n_q2[64 * 1024];
__device__ float n_k1[64 * 1024];
__device__ float n_k2[64 * 1024];

// ===========================================================================
// helpers
// ===========================================================================
__device__ __forceinline__ uint32_t smem_u32(const void* p) {
    uint32_t a;
    asm("{ .reg .u64 t; cvta.to.shared.u64 t, %1; cvt.u32.u64 %0, t; }"
        : "=r"(a) : "l"(p));
    return a;
}
__device__ __forceinline__ void cp_async16(uint32_t dst, const void* src) {
    asm volatile("cp.async.cg.shared.global [%0], [%1], 16;"
                 :: "r"(dst), "l"(src));
}
__device__ __forceinline__ void cp_commit() {
    asm volatile("cp.async.commit_group;" ::: "memory");
}
__device__ __forceinline__ void cp_wait1() {
    asm volatile("cp.async.wait_group 1;" ::: "memory");
}
__device__ __forceinline__ void cp_wait0() {
    asm volatile("cp.async.wait_group 0;" ::: "memory");
}
__device__ __forceinline__ void ldsm4(uint32_t addr, uint32_t* r) {
    asm volatile("ldmatrix.sync.aligned.m8n8.x4.shared.b16 {%0,%1,%2,%3}, [%4];"
                 : "=r"(r[0]), "=r"(r[1]), "=r"(r[2]), "=r"(r[3]) : "r"(addr));
}
__device__ __forceinline__ void ldsm4t(uint32_t addr, uint32_t* r) {
    asm volatile("ldmatrix.sync.aligned.m8n8.x4.trans.shared.b16 {%0,%1,%2,%3}, [%4];"
                 : "=r"(r[0]), "=r"(r[1]), "=r"(r[2]), "=r"(r[3]) : "r"(addr));
}
__device__ __forceinline__ void mma16816(float* d, const uint32_t* a,
                                         const uint32_t* b) {
    asm volatile(
        "mma.sync.aligned.m16n8k16.row.col.f32.f16.f16.f32 "
        "{%0,%1,%2,%3}, {%4,%5,%6,%7}, {%8,%9}, {%0,%1,%2,%3};"
        : "+f"(d[0]), "+f"(d[1]), "+f"(d[2]), "+f"(d[3])
        : "r"(a[0]), "r"(a[1]), "r"(a[2]), "r"(a[3]), "r"(b[0]), "r"(b[1]));
}
__device__ __forceinline__ float ex2f(float x) {
    float y;
    asm("ex2.approx.ftz.f32 %0, %1;" : "=f"(y) : "f"(x));
    return y;
}
__device__ __forceinline__ uint32_t pk_h2(float x, float y) {
    __half2 h = __float22half2_rn(make_float2(x, y));
    return *reinterpret_cast<uint32_t*>(&h);
}
__device__ __forceinline__ float2 unpk_h2(uint32_t u) {
    __half2 h = *reinterpret_cast<__half2*>(&u);
    return __half22float2(h);
}

// ===========================================================================
// fused fp32 -> fp16 convert for all 8 source tensors (one launch)
// ===========================================================================
extern "C" __global__ void __launch_bounds__(256)
split_all(const float* __restrict__ q, const float* __restrict__ k,
          const float* __restrict__ v, const float* __restrict__ wq,
          const float* __restrict__ wk1, const float* __restrict__ wk2,
          const float* __restrict__ wv, const float* __restrict__ wo) {
    const float* src;
    __half* dst;
    int n4;
    switch (blockIdx.y) {
        case 0: src = q;   dst = in_q; n4 = NELEM / 4; break;
        case 1: src = k;   dst = in_k; n4 = NELEM / 4; break;
        case 2: src = v;   dst = in_v; n4 = NELEM / 4; break;
        case 3: src = wq;  dst = w_f + 0 * (size_t)WSZ; n4 = WSZ / 4; break;
        case 4: src = wk1; dst = w_f + 1 * (size_t)WSZ; n4 = WSZ / 4; break;
        case 5: src = wk2; dst = w_f + 2 * (size_t)WSZ; n4 = WSZ / 4; break;
        case 6: src = wv;  dst = w_f + 3 * (size_t)WSZ; n4 = WSZ / 4; break;
        default: src = wo; dst = w_f + 4 * (size_t)WSZ; n4 = WSZ / 4; break;
    }
    int i = blockIdx.x * 256 + threadIdx.x;
    if (i >= n4) return;
    float4 val = ((const float4*)src)[i];
    uint2 o;
    o.x = pk_h2(val.x, val.y);
    o.y = pk_h2(val.z, val.w);
    ((uint2*)dst)[i] = o;
}

// ===========================================================================
// mma.sync GEMM: C[M,N] = A[M,K] @ W[N,K]^T + bias  (fp16 single product)
// CTA 128x128, K chunk 32, 512 threads (16 warps, 4m x 4n, warp tile 32x32).
// 3-stage cp.async pipeline, one barrier per K-chunk. smem 48KB; target
// 64 regs/thread => 2 CTA/SM = 32 warps/SM to hide LDSM latency.
// nm: 0 = none, 1 = q (raw), 2 = k1 (scaled NSC1), 3 = k2 (scaled NSC2)
// ===========================================================================
#define GEMM_SMEM 49152

__device__ __forceinline__ void gemm_mma_body(
    const __half* __restrict__ A, const __half* __restrict__ W,
    const float* __restrict__ bias, float* __restrict__ Cf,
    __half* __restrict__ Ch, const int nm, float* __restrict__ Nout) {
    extern __shared__ char smem[];
    const uint32_t sbase = smem_u32(smem);
    const int tid = threadIdx.x;
    const int lane = tid & 31;
    const int wid = tid >> 5;
    const int bm = blockIdx.y * 128;
    const int bn = blockIdx.x * 128;
    const int wm = (wid & 3) * 32;
    const int wnq = wid >> 2;           // 0..3
    const int wn = wnq * 32;

    const int lr = tid >> 2;            // 0..127
    const int lg = tid & 3;             // granule 0..3
    const size_t goffA = (size_t)(bm + lr) * E_DIM;
    const size_t goffW = (size_t)(bn + lr) * E_DIM;

    float acc[2][4][4];
#pragma unroll
    for (int mt = 0; mt < 2; mt++)
#pragma unroll
        for (int nt = 0; nt < 4; nt++)
#pragma unroll
            for (int e = 0; e < 4; e++) acc[mt][nt][e] = 0.0f;

#define LOAD_CHUNK(buf, kc) do {                                              \
    uint32_t d = sbase + (buf) * 16384 + lr * 64                              \
               + (((lg) ^ ((lr >> 1) & 3)) << 4);                             \
    cp_async16(d,        A + goffA + (kc) + lg * 8);                          \
    cp_async16(d + 8192, W + goffW + (kc) + lg * 8);                          \
} while (0)

    LOAD_CHUNK(0, 0);
    cp_commit();
    LOAD_CHUNK(1, 32);
    cp_commit();

    const int nk = E_DIM / 32;
    int stage = 0;
    for (int kc = 0; kc < nk; kc++) {
        cp_wait1();
        __syncthreads();
        if (kc + 2 < nk) {
            int ns = stage + 2; if (ns >= 3) ns -= 3;
            LOAD_CHUNK(ns, (kc + 2) * 32);
            cp_commit();
        }

        const uint32_t tb = sbase + stage * 16384;
#pragma unroll
        for (int s = 0; s < 2; s++) {
            uint32_t a_f[2][4];
            const int ac = s * 2 + (lane >> 4);
#pragma unroll
            for (int mt = 0; mt < 2; mt++) {
                int r = wm + mt * 16 + (lane & 15);
                uint32_t ad = tb + r * 64 + ((ac ^ ((r >> 1) & 3)) << 4);
                ldsm4(ad, a_f[mt]);
            }
            uint32_t b_f[4][2];
            const int grp = lane >> 3;
            const int bc = s * 2 + (grp & 1);
            const int br = wn + ((grp >> 1) << 3) + (lane & 7);
#pragma unroll
            for (int np = 0; np < 2; np++) {
                int r = br + np * 16;
                uint32_t bd = tb + 8192 + r * 64 + ((bc ^ ((r >> 1) & 3)) << 4);
                uint32_t qv[4];
                ldsm4(bd, qv);
                b_f[np * 2][0] = qv[0]; b_f[np * 2][1] = qv[1];
                b_f[np * 2 + 1][0] = qv[2]; b_f[np * 2 + 1][1] = qv[3];
            }
#pragma unroll
            for (int mt = 0; mt < 2; mt++)
#pragma unroll
                for (int nt = 0; nt < 4; nt++)
                    mma16816(acc[mt][nt], a_f[mt], b_f[nt]);
        }
        if (++stage >= 3) stage = 0;
    }
#undef LOAD_CHUNK

    // ---- epilogue: store C (fp16 or fp32) + per-row 32-col norm partials ----
    float ns[2][2];   // [mt][row-half]
    ns[0][0] = ns[0][1] = ns[1][0] = ns[1][1] = 0.0f;
#pragma unroll
    for (int mt = 0; mt < 2; mt++) {
        int r0 = bm + wm + mt * 16 + (lane >> 2);
#pragma unroll
        for (int nt = 0; nt < 4; nt++) {
            int cg = bn + wn + nt * 8 + ((lane & 3) << 1);
            float2 bb = *(const float2*)&bias[cg];
            float v00 = acc[mt][nt][0] + bb.x, v01 = acc[mt][nt][1] + bb.y;
            float v10 = acc[mt][nt][2] + bb.x, v11 = acc[mt][nt][3] + bb.y;
            if (Cf) {
                *(float2*)&Cf[(size_t)r0 * E_DIM + cg] = make_float2(v00, v01);
                *(float2*)&Cf[(size_t)(r0 + 8) * E_DIM + cg] = make_float2(v10, v11);
            } else {
                uint32_t p0 = pk_h2(v00, v01);
                uint32_t p1 = pk_h2(v10, v11);
                *(uint32_t*)&Ch[(size_t)r0 * E_DIM + cg] = p0;
                *(uint32_t*)&Ch[(size_t)(r0 + 8) * E_DIM + cg] = p1;
                if (nm) {
                    float2 f0 = unpk_h2(p0);
                    float2 f1 = unpk_h2(p1);
                    ns[mt][0] = fmaf(f0.x, f0.x, ns[mt][0]);
                    ns[mt][0] = fmaf(f0.y, f0.y, ns[mt][0]);
                    ns[mt][1] = fmaf(f1.x, f1.x, ns[mt][1]);
                    ns[mt][1] = fmaf(f1.y, f1.y, ns[mt][1]);
                }
            }
        }
    }
    if (nm) {
        // quad-reduce -> per-row partial over this warp's 32 cols
#pragma unroll
        for (int mt = 0; mt < 2; mt++)
#pragma unroll
            for (int hh = 0; hh < 2; hh++) {
                ns[mt][hh] += __shfl_xor_sync(0xffffffffu, ns[mt][hh], 1);
                ns[mt][hh] += __shfl_xor_sync(0xffffffffu, ns[mt][hh], 2);
            }
        float* nsbuf = (float*)smem;   // 128 rows x 4 warp-cols = 2KB
        __syncthreads();               // mainloop smem reads all done
        if ((lane & 3) == 0) {
#pragma unroll
            for (int mt = 0; mt < 2; mt++) {
                int rl = wm + mt * 16 + (lane >> 2);
                nsbuf[rl * 4 + wnq] = ns[mt][0];
                nsbuf[(rl + 8) * 4 + wnq] = ns[mt][1];
            }
        }
        __syncthreads();
        if (tid < 128) {
            const float nsc = (nm == 1) ? 1.0f : (nm == 2 ? NSC1 : NSC2);
            float h0 = (nsbuf[tid * 4 + 0] + nsbuf[tid * 4 + 1]) * nsc;
            float h1 = (nsbuf[tid * 4 + 2] + nsbuf[tid * 4 + 3]) * nsc;
            int gr = bm + tid;
            int t = gr >> 2;
            int bb_ = gr & 3;
            int hh0 = bn >> 6;
            Nout[(size_t)(bb_ * 16 + hh0) * 1024 + t] = h0;
            Nout[(size_t)(bb_ * 16 + hh0 + 1) * 1024 + t] = h1;
        }
    }
}

// Fused 4-way projection: z=0:q z=1:k1 z=2:k2 z=3:v  -> fp16 outputs + norms
extern "C" __global__ void __launch_bounds__(512, 2)
proj_kernel(const float* __restrict__ bias) {
    int z = blockIdx.z;
    if (z == 0)
        gemm_mma_body(in_q, w_f, bias, nullptr, o_q, 1, n_q2);
    else if (z == 1)
        gemm_mma_body(in_k, w_f + (size_t)WSZ, bias + E_DIM, nullptr,
                      o_k1, 2, n_k1);
    else if (z == 2)
        gemm_mma_body(in_k, w_f + 2 * (size_t)WSZ, bias + 2 * E_DIM, nullptr,
                      o_k2, 3, n_k2);
    else
        gemm_mma_body(in_v, w_f + 3 * (size_t)WSZ, bias + 3 * E_DIM, nullptr,
                      o_v, 0, nullptr);
}

extern "C" __global__ void __launch_bounds__(512, 2)
out_kernel(const float* __restrict__ bias, float* __restrict__ C) {
    gemm_mma_body(ao_f, w_f + (size_t)4 * WSZ, bias, C, nullptr, 0, nullptr);
}

// ===========================================================================
// Tensorized Gaussian-kernel attention (fp16 single product).
// Block = (64 q rows, bh), 256 threads = 8 warps (4 m-strips x 2 s-halves).
// ===========================================================================
#define AT_ORED 0
#define AT_DEN  8704
#define AT_BUF0 9216
#define AT_BUFSZ 25088
#define AT_K1 0
#define AT_K2 8192
#define AT_V  16384
#define AT_N1 24576
#define AT_N2 24832
#define ATTN_SMEM (AT_BUF0 + 2 * AT_BUFSZ)

extern "C" __global__ void __launch_bounds__(256, 2)
attn_kernel(const float* __restrict__ pi) {
    extern __shared__ char smem[];
    const uint32_t sb = smem_u32(smem);
    const int tid = threadIdx.x;
    const int lane = tid & 31;
    const int wid = tid >> 5;
    const int wm = (wid & 3) * 16;
    const int wn = wid >> 2;
    const int qt = blockIdx.x;
    const int bh = blockIdx.y;
    const int b = bh >> 4;
    const int h = bh & 15;
    const int q0 = qt * 64;

    const float p1 = fminf(fmaxf(fabsf(pi[h]), 1e-6f), 2.0f);
    const float p2 = fminf(fmaxf(fabsf(pi[H_NUM + h]), 1e-6f), 2.0f);

    const int lr = tid >> 2;
    const int lc = (tid & 3) * 2;
    const size_t grow = (size_t)h * HD;

#define LOADKV(buf, s0) do {                                                      \
    uint32_t bdst = sb + AT_BUF0 + (buf) * AT_BUFSZ;                              \
    size_t gsrc = ((size_t)((s0) + lr) * B_SZ + b) * E_DIM + grow;                \
    _Pragma("unroll")                                                             \
    for (int j = 0; j < 2; j++) {                                                 \
        int c = lc + j;                                                           \
        uint32_t d = bdst + lr * 128 + ((c ^ (lr & 7)) << 4);                     \
        cp_async16(d + AT_K1, o_k1 + gsrc + c * 8);                               \
        cp_async16(d + AT_K2, o_k2 + gsrc + c * 8);                               \
        cp_async16(d + AT_V,  o_v  + gsrc + c * 8);                               \
    }                                                                             \
    if (tid < 16)                                                                 \
        cp_async16(bdst + AT_N1 + tid * 16,                                       \
                   n_k1 + (size_t)bh * 1024 + (s0) + tid * 4);                    \
    else if (tid < 32)                                                            \
        cp_async16(bdst + AT_N2 + (tid - 16) * 16,                                \
                   n_k2 + (size_t)bh * 1024 + (s0) + (tid - 16) * 4);             \
} while (0)

    // ---- Q fragments + q2 straight into registers ----
    uint32_t qf[4][4];
    {
        const int ra = q0 + wm + (lane >> 2);
        const size_t qa = ((size_t)ra * B_SZ + b) * E_DIM + grow;
        const size_t qb = qa + (size_t)8 * B_SZ * E_DIM;
#pragma unroll
        for (int kk = 0; kk < 4; kk++) {
            const int c0 = kk * 16 + 2 * (lane & 3);
            qf[kk][0] = *(const uint32_t*)&o_q[qa + c0];
            qf[kk][1] = *(const uint32_t*)&o_q[qb + c0];
            qf[kk][2] = *(const uint32_t*)&o_q[qa + c0 + 8];
            qf[kk][3] = *(const uint32_t*)&o_q[qb + c0 + 8];
        }
    }
    const float q2a = n_q2[(size_t)bh * 1024 + q0 + wm + (lane >> 2)];
    const float q2b = n_q2[(size_t)bh * 1024 + q0 + wm + (lane >> 2) + 8];
    const float qc1a = NSC1 * q2a, qc2a = NSC2 * q2a;
    const float qc1b = NSC1 * q2b, qc2b = NSC2 * q2b;

    LOADKV(0, 0);
    cp_commit();

    float O[8][4];
#pragma unroll
    for (int nt = 0; nt < 8; nt++)
#pragma unroll
        for (int e = 0; e < 4; e++) O[nt][e] = 0.0f;
    float den0 = 0.0f, den1 = 0.0f;

    for (int st = 0; st < 16; st++) {
        cp_wait0();
        __syncthreads();
        if (st < 15) { LOADKV((st + 1) & 1, (st + 1) * 64); cp_commit(); }

        const uint32_t bb = sb + AT_BUF0 + (st & 1) * AT_BUFSZ;
        char* bbp = smem + AT_BUF0 + (st & 1) * AT_BUFSZ;

        float S1[4][4], S2[4][4];
#pragma unroll
        for (int nt = 0; nt < 4; nt++)
#pragma unroll
            for (int e = 0; e < 4; e++) { S1[nt][e] = 0.0f; S2[nt][e] = 0.0f; }

        // ---- QK over this warp's 32-key half ----
#pragma unroll
        for (int kk = 0; kk < 4; kk++) {
            const int grp = lane >> 3;
            const int c = kk * 2 + (grp & 1);
            const int rb = wn * 32 + ((grp >> 1) << 3) + (lane & 7);
            uint32_t b1[4][2], b2[4][2];
#pragma unroll
            for (int np = 0; np < 2; np++) {
                int r = rb + np * 16;
                uint32_t ra = bb + r * 128 + ((c ^ (r & 7)) << 4);
                uint32_t qv[4];
                ldsm4(ra + AT_K1, qv);
                b1[np*2][0]=qv[0]; b1[np*2][1]=qv[1];
                b1[np*2+1][0]=qv[2]; b1[np*2+1][1]=qv[3];
                ldsm4(ra + AT_K2, qv);
                b2[np*2][0]=qv[0]; b2[np*2][1]=qv[1];
                b2[np*2+1][0]=qv[2]; b2[np*2+1][1]=qv[3];
            }
#pragma unroll
            for (int nt = 0; nt < 4; nt++) {
                mma16816(S1[nt], qf[kk], b1[nt]);
                mma16816(S2[nt], qf[kk], b2[nt]);
            }
        }

        // ---- weights: w = p1*ex2(SC1*S1 + t1) + p2*ex2(SC2*S2 + t2) ----
        uint32_t wA[2][4];
        {
            const float* k1p = (const float*)(bbp + AT_N1);
            const float* k2p = (const float*)(bbp + AT_N2);
#pragma unroll
            for (int nt = 0; nt < 4; nt++) {
                const int cp0 = wn * 32 + nt * 8 + 2 * (lane & 3);
                const float k1a = k1p[cp0], k1b = k1p[cp0 + 1];
                const float k2a = k2p[cp0], k2b = k2p[cp0 + 1];
                float w00 = fmaf(p1, ex2f(fmaf(SC1, S1[nt][0], qc1a + k1a)),
                                 p2 * ex2f(fmaf(SC2, S2[nt][0], qc2a + k2a)));
                float w01 = fmaf(p1, ex2f(fmaf(SC1, S1[nt][1], qc1a + k1b)),
                                 p2 * ex2f(fmaf(SC2, S2[nt][1], qc2a + k2b)));
                float w10 = fmaf(p1, ex2f(fmaf(SC1, S1[nt][2], qc1b + k1a)),
                                 p2 * ex2f(fmaf(SC2, S2[nt][2], qc2b + k2a)));
                float w11 = fmaf(p1, ex2f(fmaf(SC1, S1[nt][3], qc1b + k1b)),
                                 p2 * ex2f(fmaf(SC2, S2[nt][3], qc2b + k2b)));
                // round to fp16 first; accumulate den from the ROUNDED values
                uint32_t h0 = pk_h2(w00, w01);
                uint32_t h1 = pk_h2(w10, w11);
                float2 r0f = unpk_h2(h0);
                float2 r1f = unpk_h2(h1);
                den0 += r0f.x + r0f.y;
                den1 += r1f.x + r1f.y;
                const int kk = nt >> 1;
                const int e = (nt & 1) * 2;
                wA[kk][e]     = h0;
                wA[kk][e + 1] = h1;
            }
        }

        // ---- AV: O(partial over s-half) += w @ V, all 64 cols ----
#pragma unroll
        for (int kk = 0; kk < 2; kk++) {
            uint32_t bv[8][2];
            {
                int r = wn * 32 + kk * 16 + (lane & 15);
                uint32_t rowa = bb + AT_V + r * 128;
#pragma unroll
                for (int cb = 0; cb < 8; cb += 2) {
                    int g0 = cb + (lane >> 4);
                    uint32_t qv[4];
                    ldsm4t(rowa + ((g0 ^ (r & 7)) << 4), qv);
                    bv[cb][0]=qv[0]; bv[cb][1]=qv[1];
                    bv[cb+1][0]=qv[2]; bv[cb+1][1]=qv[3];
                }
            }
#pragma unroll
            for (int nt = 0; nt < 8; nt++)
                mma16816(O[nt], wA[kk], bv[nt]);
        }
    }
#undef LOADKV

    // ---- cross-warp reduction of O and den over the two s-halves ----
    den0 += __shfl_xor_sync(0xffffffffu, den0, 1);
    den0 += __shfl_xor_sync(0xffffffffu, den0, 2);
    den1 += __shfl_xor_sync(0xffffffffu, den1, 1);
    den1 += __shfl_xor_sync(0xffffffffu, den1, 2);

    float* dens = (float*)(smem + AT_DEN);
    float* ored = (float*)(smem + AT_ORED);   // pitch 34 floats, 64 rows
    const int r0 = wm + (lane >> 2);
    __syncthreads();
    if ((lane & 3) == 0) {
        dens[r0 * 2 + wn] = den0;
        dens[(r0 + 8) * 2 + wn] = den1;
    }
    // chunk 0: nt 0..3
    if (wn == 1) {
#pragma unroll
        for (int nt = 0; nt < 4; nt++) {
            const int c = nt * 8 + 2 * (lane & 3);
            *(float2*)&ored[r0 * 34 + c] = make_float2(O[nt][0], O[nt][1]);
            *(float2*)&ored[(r0 + 8) * 34 + c] = make_float2(O[nt][2], O[nt][3]);
        }
    }
    __syncthreads();
    float ia = 0.0f, ib = 0.0f;
    if (wn == 0) {
        ia = 1.0f / (dens[r0 * 2] + dens[r0 * 2 + 1] + 1e-6f);
        ib = 1.0f / (dens[(r0 + 8) * 2] + dens[(r0 + 8) * 2 + 1] + 1e-6f);
#pragma unroll
        for (int nt = 0; nt < 4; nt++) {
            const int c = nt * 8 + 2 * (lane & 3);
            float2 pa = *(const float2*)&ored[r0 * 34 + c];
            float2 pb = *(const float2*)&ored[(r0 + 8) * 34 + c];
            uint32_t h0 = pk_h2((O[nt][0] + pa.x) * ia, (O[nt][1] + pa.y) * ia);
            uint32_t h1 = pk_h2((O[nt][2] + pb.x) * ib, (O[nt][3] + pb.y) * ib);
            size_t i0 = ((size_t)(q0 + r0) * B_SZ + b) * E_DIM + grow + c;
            size_t i1 = i0 + (size_t)8 * B_SZ * E_DIM;
            *(uint32_t*)&ao_f[i0] = h0;
            *(uint32_t*)&ao_f[i1] = h1;
        }
    }
    __syncthreads();
    // chunk 1: nt 4..7
    if (wn == 1) {
#pragma unroll
        for (int nt = 4; nt < 8; nt++) {
            const int c = (nt - 4) * 8 + 2 * (lane & 3);
            *(float2*)&ored[r0 * 34 + c] = make_float2(O[nt][0], O[nt][1]);
            *(float2*)&ored[(r0 + 8) * 34 + c] = make_float2(O[nt][2], O[nt][3]);
        }
    }
    __syncthreads();
    if (wn == 0) {
#pragma unroll
        for (int nt = 4; nt < 8; nt++) {
            const int c = (nt - 4) * 8 + 2 * (lane & 3);
            float2 pa = *(const float2*)&ored[r0 * 34 + c];
            float2 pb = *(const float2*)&ored[(r0 + 8) * 34 + c];
            uint32_t h0 = pk_h2((O[nt][0] + pa.x) * ia, (O[nt][1] + pa.y) * ia);
            uint32_t h1 = pk_h2((O[nt][2] + pb.x) * ib, (O[nt][3] + pb.y) * ib);
            const int cg = nt * 8 + 2 * (lane & 3);
            size_t i0 = ((size_t)(q0 + r0) * B_SZ + b) * E_DIM + grow + cg;
            size_t i1 = i0 + (size_t)8 * B_SZ * E_DIM;
            *(uint32_t*)&ao_f[i0] = h0;
            *(uint32_t*)&ao_f[i1] = h1;
        }
    }
}

// ---------------------------------------------------------------------------
extern "C" void kernel_launch(void* const* d_in, const int* in_sizes, int n_in,
                              void* d_out, int out_size) {
    const float* query = (const float*)d_in[0];
    const float* key   = (const float*)d_in[1];
    const float* value = (const float*)d_in[2];
    const float* wq    = (const float*)d_in[3];
    const float* wk1   = (const float*)d_in[4];
    const float* wk2   = (const float*)d_in[5];
    const float* wv    = (const float*)d_in[6];
    const float* bias  = (const float*)d_in[7];
    const float* wo    = (const float*)d_in[8];
    const float* bo    = (const float*)d_in[9];
    const float* pi    = (const float*)d_in[10];
    float* out = (float*)d_out;

    cudaFuncSetAttribute(proj_kernel,
                         cudaFuncAttributeMaxDynamicSharedMemorySize, GEMM_SMEM);
    cudaFuncSetAttribute(out_kernel,
                         cudaFuncAttributeMaxDynamicSharedMemorySize, GEMM_SMEM);
    cudaFuncSetAttribute(attn_kernel,
                         cudaFuncAttributeMaxDynamicSharedMemorySize, ATTN_SMEM);

    dim3 gsplit(4096, 8);
    split_all<<<gsplit, 256>>>(query, key, value, wq, wk1, wk2, wv, wo);

    dim3 gproj(8, 32, 4);
    proj_kernel<<<gproj, 512, GEMM_SMEM>>>(bias);

    dim3 gattn(16, 64);
    attn_kernel<<<gattn, 256, ATTN_SMEM>>>(pi);

    dim3 gout(8, 32);
    out_kernel<<<gout, 512, GEMM_SMEM>>>(bo, out);
}